// round 1
// baseline (speedup 1.0000x reference)
#include <cuda_runtime.h>
#include <cstdint>

#define BB 64
#define RR 32
#define NN 16384
#define DD 64
#define OO 8
#define CHUNKS 8
#define NC (NN / CHUNKS)   // 2048 rows per block

// Scratch: masked sum of normalized context vectors + valid counts.
__device__ float g_s[BB * DD];
__device__ float g_cnt[BB];

__global__ void zero_kernel() {
    int i = blockIdx.x * blockDim.x + threadIdx.x;
    if (i < BB * DD) g_s[i] = 0.0f;
    if (i < BB) g_cnt[i] = 0.0f;
}

// One block per (b, chunk). Phase A: scan masks (int4-vectorized), compact
// valid n's into shared list. Phase B: warps gather h_context rows for valid
// n's only (~0.74% density), normalize, accumulate.
__global__ void __launch_bounds__(256) accum_kernel(
    const float* __restrict__ h_context,
    const int* __restrict__ center_o,
    const int* __restrict__ o_types,
    const unsigned int* __restrict__ adj,   // bool-as-32-bit-word (i32 or f32 0/1)
    const unsigned int* __restrict__ two)
{
    __shared__ int s_idx[NC];
    __shared__ int s_count;
    __shared__ float s_acc[DD];

    const int b = blockIdx.x / CHUNKS;
    const int c = blockIdx.x % CHUNKS;
    const int tid = threadIdx.x;

    if (tid == 0) s_count = 0;
    if (tid < DD) s_acc[tid] = 0.0f;
    __syncthreads();

    const int co = center_o[b];
    const int base = b * NN + c * NC;

    const int4*  ot4 = reinterpret_cast<const int4*>(o_types + base);
    const uint4* a4  = reinterpret_cast<const uint4*>(adj + base);
    const uint4* t4  = reinterpret_cast<const uint4*>(two + base);

    // Phase A: mask scan + compaction (NC/4 = 512 int4 iters over 256 threads)
    for (int i = tid; i < NC / 4; i += 256) {
        int4 ot = ot4[i];
        uint4 a = a4[i];
        uint4 t = t4[i];
        int n0 = c * NC + i * 4;
        if (ot.x == co && (a.x | t.x)) s_idx[atomicAdd(&s_count, 1)] = n0 + 0;
        if (ot.y == co && (a.y | t.y)) s_idx[atomicAdd(&s_count, 1)] = n0 + 1;
        if (ot.z == co && (a.z | t.z)) s_idx[atomicAdd(&s_count, 1)] = n0 + 2;
        if (ot.w == co && (a.w | t.w)) s_idx[atomicAdd(&s_count, 1)] = n0 + 3;
    }
    __syncthreads();

    const int cnt = s_count;
    const int warp = tid >> 5;
    const int lane = tid & 31;

    // Phase B: warps cooperatively process compacted rows.
    // Each lane owns 2 of the 64 dims (float2).
    float accx = 0.0f, accy = 0.0f;
    const float2* ctx2 = reinterpret_cast<const float2*>(
        h_context + (size_t)b * NN * DD);

    for (int i = warp; i < cnt; i += 8) {
        int n = s_idx[i];
        float2 x = __ldg(ctx2 + (size_t)n * (DD / 2) + lane);
        float sq = x.x * x.x + x.y * x.y;
        #pragma unroll
        for (int o = 16; o; o >>= 1)
            sq += __shfl_xor_sync(0xffffffffu, sq, o);
        float rinv = rsqrtf(fmaxf(sq, 1e-12f));
        accx += x.x * rinv;
        accy += x.y * rinv;
    }
    atomicAdd(&s_acc[2 * lane + 0], accx);
    atomicAdd(&s_acc[2 * lane + 1], accy);
    __syncthreads();

    if (tid < DD) atomicAdd(&g_s[b * DD + tid], s_acc[tid]);
    if (tid == 0) atomicAdd(&g_cnt[b], (float)cnt);
}

// One block per b, one warp per r (32 warps = 1024 threads).
__global__ void __launch_bounds__(1024) finalize_kernel(
    const float* __restrict__ l_local,
    const float* __restrict__ lambda_so,
    const int* __restrict__ center_o,
    float* __restrict__ out)
{
    const int b = blockIdx.x;
    const int tid = threadIdx.x;

    __shared__ float sv[DD];
    __shared__ float scnt;
    if (tid < DD) sv[tid] = g_s[b * DD + tid];
    if (tid == 0) scnt = g_cnt[b];
    __syncthreads();

    const int r = tid >> 5;
    const int lane = tid & 31;

    const float2* row = reinterpret_cast<const float2*>(
        l_local + ((size_t)b * RR + r) * DD);
    float2 x = row[lane];

    float sq = x.x * x.x + x.y * x.y;
    float dp = x.x * sv[2 * lane] + x.y * sv[2 * lane + 1];
    #pragma unroll
    for (int o = 16; o; o >>= 1) {
        sq += __shfl_xor_sync(0xffffffffu, sq, o);
        dp += __shfl_xor_sync(0xffffffffu, dp, o);
    }

    if (lane == 0) {
        float rinv = rsqrtf(fmaxf(sq, 1e-12f));
        float cnt = scnt;
        float avg = dp * rinv / fmaxf(cnt, 1e-9f);
        int co = center_o[b];
        float lam = lambda_so[r * OO + co];
        float w = fmaxf(lam / fmaxf(cnt, 1.0f), 0.0f) * (1.0f - avg);
        out[b * RR + r] = w;
    }
}

extern "C" void kernel_launch(void* const* d_in, const int* in_sizes, int n_in,
                              void* d_out, int out_size) {
    const float*        l_local   = (const float*)d_in[0];
    const float*        h_context = (const float*)d_in[1];
    const float*        lambda_so = (const float*)d_in[2];
    const int*          center_o  = (const int*)d_in[3];
    const int*          o_types   = (const int*)d_in[4];
    const unsigned int* adj       = (const unsigned int*)d_in[5];
    const unsigned int* two       = (const unsigned int*)d_in[6];
    float*              out       = (float*)d_out;

    zero_kernel<<<(BB * DD + 255) / 256, 256>>>();
    accum_kernel<<<BB * CHUNKS, 256>>>(h_context, center_o, o_types, adj, two);
    finalize_kernel<<<BB, 1024>>>(l_local, lambda_so, center_o, out);
}